// round 4
// baseline (speedup 1.0000x reference)
#include <cuda_runtime.h>

#define W 512
#define NB 16
#define NPIX (W * W)
#define NTOT (NB * NPIX)
#define CELL_W 0.390625f            // 200/512, exactly representable

#define TX 32
#define TY 16
#define HALO 2
#define SW (TX + 2 * HALO)          // 36
#define SH (TY + 2 * HALO)          // 20
#define NTHREADS (TX * TY)          // 512

// Scratch state (allowed: __device__ globals, not cudaMalloc)
__device__ float g_terrA[NTOT];
__device__ float g_terrB[NTOT];
__device__ float g_sed[NTOT];
__device__ float g_wat[NTOT];
__device__ float g_vel[NTOT];

template <bool FIRST, bool LAST>
__global__ __launch_bounds__(NTHREADS, 3) void erosion_step(
    const float* __restrict__ ext_in,   // input_terrain (only when FIRST)
    float* __restrict__ final_out,      // d_out (only when LAST)
    const float* __restrict__ rain,     // this iteration's (W,W) rainfall slice
    int parity,
    const float* __restrict__ s_rain_rate,
    const float* __restrict__ s_evap,
    const float* __restrict__ s_mhd,
    const float* __restrict__ s_heps,
    const float* __restrict__ s_grav,
    const float* __restrict__ s_ks,
    const float* __restrict__ s_diss,
    const float* __restrict__ s_dep)
{
    __shared__ float sT[SH * SW];

    const int tx = threadIdx.x, ty = threadIdx.y;
    const int bx = blockIdx.x * TX, by = blockIdx.y * TY;
    const int b  = blockIdx.z;
    const int i  = by + ty;
    const int j  = bx + tx;
    const int idx = b * NPIX + i * W + j;

    const float* tin = FIRST ? (ext_in + b * NPIX) : ((parity ? g_terrA : g_terrB) + b * NPIX);
    float* tout = parity ? g_terrB : g_terrA;

    // ---- early loads (overlap with smem fill) ----
    float sed, wat, vel;
    if (FIRST) { sed = 0.0f; wat = 0.0f; vel = 0.0f; }
    else       { sed = g_sed[idx]; wat = g_wat[idx]; vel = g_vel[idx]; }
    const float rv = __ldg(&rain[i * W + j]);

    const float rainr = fmaxf(__ldg(s_rain_rate), 0.0f);
    const float evapr = fmaxf(__ldg(s_evap), 0.0f);
    const float mhd   = __ldg(s_mhd);
    const float heps  = __ldg(s_heps);
    const float gravr = fmaxf(__ldg(s_grav), 0.0f);
    const float ksr   = fmaxf(__ldg(s_ks), 0.0f);
    const float dissr = __ldg(s_diss);
    const float depr  = __ldg(s_dep);

    // ---- fill smem terrain tile with halo=2; OOB cells get exactly 1.0f ----
    // (gather reads sT - 1 then adds 1 back: OOB -> 0 contribution, bit-exact
    //  match to the reference's masked (t-1) gather)
    const int tid = ty * TX + tx;
    #pragma unroll
    for (int k = tid; k < SH * SW; k += NTHREADS) {
        const int li0 = k / SW, lj0 = k % SW;
        const int gi = by + li0 - HALO;
        const int gj = bx + lj0 - HALO;
        float v = 1.0f;
        if (gi >= 0 && gi < W && gj >= 0 && gj < W) {
            v = __ldg(&tin[gi * W + gj]);
            if (FIRST) v = (1.0f - v) * 0.5f;
        }
        sT[k] = v;
    }
    __syncthreads();

    const int li = ty + HALO, lj = tx + HALO;
    const float tc = sT[li * SW + lj];

    // ---- simple_gradient (factor term exactly 0: mag >= 3.16e-6 > 1e-10) ----
    float dx, dy;
    if (i == 0)          dx = 0.5f * (tc * 1.1f - tc);
    else if (i == W - 1) dx = 0.5f * (tc * 0.9f - tc);
    else                 dx = 0.5f * (sT[(li + 1) * SW + lj] - sT[(li - 1) * SW + lj]);
    if (j == 0)          dy = 0.5f * (tc * 1.1f - tc);
    else if (j == W - 1) dy = 0.5f * (tc * 0.9f - tc);
    else                 dy = 0.5f * (sT[li * SW + lj + 1] - sT[li * SW + lj - 1]);

    const float mag = sqrtf(dx * dx + dy * dy + 1e-11f);
    const float fdx = dx / mag;     // IEEE division, matches reference fdx
    const float fdy = dy / mag;

    // water = water + relu(rain_rate) * rain
    wat += rainr * rv;

    // ---- bilinear_sample(terrain, -gradient): global coords, like reference ----
    const float fx = (float)j - fdx;
    const float fy = (float)i - fdy;
    const float x0f = floorf(fx);
    const float y0f = floorf(fy);
    const float wx1 = fx - x0f;
    const float wy1 = fy - y0f;
    // shift to local smem coords (exact integer arithmetic)
    const int lx0 = (int)x0f - bx + HALO;   // in [0, SW-2]
    const int ly0 = (int)y0f - by + HALO;   // in [0, SH-2]

    const float g00 = sT[ly0 * SW + lx0]           - 1.0f;
    const float g10 = sT[ly0 * SW + lx0 + 1]       - 1.0f;
    const float g01 = sT[(ly0 + 1) * SW + lx0]     - 1.0f;
    const float g11 = sT[(ly0 + 1) * SW + lx0 + 1] - 1.0f;
    const float neighbor =
        (1.0f - wy1) * ((1.0f - wx1) * g00 + wx1 * g10) +
        wy1 * ((1.0f - wx1) * g01 + wx1 * g11) + 1.0f;

    // ---- erosion / deposition (same expression forms as Round 1) ----
    const float hd = tc - neighbor;
    const float hds = (hd - heps > 0.0f) ? 1.0f : 0.0f;
    const float nhd = hds * fmaxf(hd, mhd);
    const float sed_cap = nhd / CELL_W * vel * wat * ksr;
    const float ftb = (hd < 0.0f) ? 1.0f : 0.0f;
    const float fst = fminf(fmaxf(-hd, 0.0f), sed);
    const float sdiff = sed - sed_cap;
    const float third = (1.0f - ftb) *
        (fmaxf(sdiff * depr, 0.0f) - fmaxf(-sdiff * dissr, 0.0f));
    const float dep = fmaxf(-fmaxf(hd, 0.0f), fst + third);
    sed = sed - dep;
    const float tn = tc + dep;

    // ---- displace: three summed products, matching t1 + t2 + t3 ----
    const float w2 = fmaxf(1.0f - fabsf(fdy), 0.0f);
    const float e1 = (j == W - 1) ? 0.0f : fmaxf(-fdy, 0.0f);
    const float e3 = (j == 0)     ? 0.0f : fmaxf(fdy, 0.0f);

    if (LAST) {
        // fused output transform: relu(1 + (1 - 2t)) - 1
        final_out[idx] = fmaxf(1.0f + (1.0f - tn * 2.0f), 0.0f) - 1.0f;
    } else {
        tout[idx]  = tn;
        g_sed[idx] = e1 * sed + w2 * sed + e3 * sed;
        const float watd = e1 * wat + w2 * wat + e3 * wat;
        g_wat[idx] = watd * (1.0f - evapr);
        g_vel[idx] = gravr * hd / CELL_W;
    }
}

extern "C" void kernel_launch(void* const* d_in, const int* in_sizes, int n_in,
                              void* d_out, int out_size)
{
    const float* input_terrain = (const float*)d_in[0];
    const float* rainfall      = (const float*)d_in[1];  // (10, 512, 512)
    // d_in[2] = random_gradient: provably unused (factor == 0 exactly)
    const float* s_rain_rate   = (const float*)d_in[3];
    const float* s_evap        = (const float*)d_in[4];
    const float* s_mhd         = (const float*)d_in[5];
    const float* s_heps        = (const float*)d_in[6];
    const float* s_grav        = (const float*)d_in[7];
    const float* s_ks          = (const float*)d_in[8];
    const float* s_diss        = (const float*)d_in[9];
    const float* s_dep         = (const float*)d_in[10];
    float* out = (float*)d_out;

    dim3 blk(TX, TY, 1);
    dim3 grd(W / TX, W / TY, NB);

    for (int it = 0; it < 10; ++it) {
        const float* rain = rainfall + it * NPIX;
        const int parity = it & 1;
        if (it == 0) {
            erosion_step<true, false><<<grd, blk>>>(
                input_terrain, out, rain, parity,
                s_rain_rate, s_evap, s_mhd, s_heps, s_grav, s_ks, s_diss, s_dep);
        } else if (it == 9) {
            erosion_step<false, true><<<grd, blk>>>(
                input_terrain, out, rain, parity,
                s_rain_rate, s_evap, s_mhd, s_heps, s_grav, s_ks, s_diss, s_dep);
        } else {
            erosion_step<false, false><<<grd, blk>>>(
                input_terrain, out, rain, parity,
                s_rain_rate, s_evap, s_mhd, s_heps, s_grav, s_ks, s_diss, s_dep);
        }
    }
}